// round 2
// baseline (speedup 1.0000x reference)
#include <cuda_runtime.h>
#include <cuda_bf16.h>
#include <math.h>

// Problem constants
#define NB 8
#define SS 2048
#define DM 1024
#define NH 16
#define DH 64
#define MROWS (NB * SS)           // 16384
#define ELEMS ((size_t)MROWS * DM) // 16,777,216

// Scratch (device globals — no allocation allowed)
__device__ float g_Q[ELEMS];      // Q = Q_seq @ WQ              [b,s,1024]
__device__ float g_Kp[ELEMS];     // Kp = K_seq @ WK             [b,s,1024]
__device__ float g_QAK[ELEMS];    // QAK                         [b,h,s,dh] contiguous
__device__ float g_logits[NB * NH * SS]; // [b,e,s] (reused for alpha then beta)
__device__ float g_qglob[NB * NH * DH];  // [b,h,dh]
__device__ float g_kglob[NB * NH * DH];  // [b,h,dh] == [b,1024]
__device__ float g_WaT[NH * DM];
__device__ float g_WbT[NH * DM];

// ---------------------------------------------------------------------------
// Tiled SGEMM: C[M,N] = A[M,K] @ B[K,N]  (+ optional per-(batch,k) A scaling
// and +residual epilogue for the final projection).
// BM=BN=128, BK=8, 256 threads, 8x8 per-thread tile.
// M multiple of 128, N multiple of 128, K multiple of 8 (all true here).
// ---------------------------------------------------------------------------
template <bool SCALED>
__global__ __launch_bounds__(256) void sgemm128(
    const float* __restrict__ A, const float* __restrict__ B,
    float* __restrict__ C,
    const float* __restrict__ scale,     // [NB,1024] per-(b,k) A scale (SCALED)
    const float* __restrict__ residual,  // [M,N] or nullptr
    int M, int N, int K)
{
    const int BM = 128, BN = 128, BK = 8, TM = 8, TN = 8;
    __shared__ float As[BK][BM];
    __shared__ float Bs[BK][BN];

    const int tid  = threadIdx.x;
    const int trow = tid / 16;      // 0..15
    const int tcol = tid % 16;      // 0..15

    const int brow = blockIdx.y;
    const int bcol = blockIdx.x;

    // A-tile load mapping: 128 rows x 8 cols = 256 float4 (2 per row)
    const int aRow  = tid >> 1;           // 0..127
    const int aCol4 = (tid & 1) * 4;      // 0 or 4
    // B-tile load mapping: 8 rows x 128 cols = 256 float4
    const int bRow  = tid >> 5;           // 0..7
    const int bCol4 = (tid & 31) * 4;     // 0..124

    const float* Aptr = A + (size_t)(brow * BM) * K;
    const float* Bptr = B + bcol * BN;

    float acc[TM][TN];
#pragma unroll
    for (int i = 0; i < TM; i++)
#pragma unroll
        for (int j = 0; j < TN; j++) acc[i][j] = 0.0f;

    const int grow = brow * BM + aRow;
    const float* srowp = nullptr;
    if (SCALED) srowp = scale + (size_t)(grow >> 11) * 1024;

    for (int k0 = 0; k0 < K; k0 += BK) {
        float4 av = *(const float4*)(Aptr + (size_t)aRow * K + k0 + aCol4);
        if (SCALED) {
            const float4 sv = *(const float4*)(srowp + k0 + aCol4);
            av.x *= sv.x; av.y *= sv.y; av.z *= sv.z; av.w *= sv.w;
        }
        As[aCol4 + 0][aRow] = av.x;
        As[aCol4 + 1][aRow] = av.y;
        As[aCol4 + 2][aRow] = av.z;
        As[aCol4 + 3][aRow] = av.w;

        const float4 bv = *(const float4*)(Bptr + (size_t)(k0 + bRow) * N + bCol4);
        *(float4*)&Bs[bRow][bCol4] = bv;

        __syncthreads();

#pragma unroll
        for (int kk = 0; kk < BK; kk++) {
            float ar[TM], br[TN];
            const float4 a0 = *(const float4*)&As[kk][trow * TM];
            const float4 a1 = *(const float4*)&As[kk][trow * TM + 4];
            ar[0]=a0.x; ar[1]=a0.y; ar[2]=a0.z; ar[3]=a0.w;
            ar[4]=a1.x; ar[5]=a1.y; ar[6]=a1.z; ar[7]=a1.w;
            const float4 b0 = *(const float4*)&Bs[kk][tcol * TN];
            const float4 b1 = *(const float4*)&Bs[kk][tcol * TN + 4];
            br[0]=b0.x; br[1]=b0.y; br[2]=b0.z; br[3]=b0.w;
            br[4]=b1.x; br[5]=b1.y; br[6]=b1.z; br[7]=b1.w;
#pragma unroll
            for (int i = 0; i < TM; i++)
#pragma unroll
                for (int j = 0; j < TN; j++)
                    acc[i][j] = fmaf(ar[i], br[j], acc[i][j]);
        }
        __syncthreads();
    }

    // Epilogue (float4 stores, optional residual)
#pragma unroll
    for (int i = 0; i < TM; i++) {
        const size_t row = (size_t)brow * BM + trow * TM + i;
#pragma unroll
        for (int j4 = 0; j4 < TN; j4 += 4) {
            const size_t col = (size_t)bcol * BN + tcol * TN + j4;
            float4 v = make_float4(acc[i][j4], acc[i][j4+1], acc[i][j4+2], acc[i][j4+3]);
            if (residual) {
                const float4 r = *(const float4*)(residual + row * N + col);
                v.x += r.x; v.y += r.y; v.z += r.z; v.w += r.w;
            }
            *(float4*)(C + row * N + col) = v;
        }
    }
}

// ---------------------------------------------------------------------------
// Transpose small weight [1024,16] -> [16][1024]
// ---------------------------------------------------------------------------
__global__ void transpose_w(const float* __restrict__ W, float* __restrict__ WT)
{
    int i = blockIdx.x * 256 + threadIdx.x;
    if (i < DM * NH) {
        int j = i >> 4, e = i & 15;
        WT[e * DM + j] = W[i];
    }
}

// ---------------------------------------------------------------------------
// Row logits: logits[b,e,s] = scaleF * dot(rows[r,:], WT[e,:]),  r = b*S+s
// rows: flat [16384, 1024]. One block per row; 8 warps -> 16 outputs.
// ---------------------------------------------------------------------------
__global__ __launch_bounds__(256) void row_logits(
    const float* __restrict__ rows, const float* __restrict__ WT,
    float* __restrict__ logits, float scaleF)
{
    const int r = blockIdx.x;
    const float* row = rows + (size_t)r * DM;
    __shared__ float srow[DM];
    const int tid = threadIdx.x;
    for (int i = tid; i < DM / 4; i += 256)
        *(float4*)&srow[i * 4] = *(const float4*)(row + i * 4);
    __syncthreads();

    const int warp = tid >> 5, lane = tid & 31;
#pragma unroll
    for (int e = warp; e < NH; e += 8) {
        const float* w = WT + e * DM;
        float p = 0.0f;
        for (int j = lane; j < DM; j += 32) p = fmaf(srow[j], w[j], p);
#pragma unroll
        for (int o = 16; o; o >>= 1) p += __shfl_xor_sync(0xffffffffu, p, o);
        if (lane == 0) {
            const int b = r >> 11, s = r & (SS - 1);
            logits[((size_t)(b * NH + e)) * SS + s] = p * scaleF;
        }
    }
}

// ---------------------------------------------------------------------------
// Fused softmax over s + weighted pooling:
//   w = softmax(logits[bh, :]);  out[bh, d] = sum_s w[s] * src[base + s*sStride + d]
// base = b*bStride + h*hStride. One block per (b,h); 256 threads.
// ---------------------------------------------------------------------------
__global__ __launch_bounds__(256) void softmax_pool(
    const float* __restrict__ logits, const float* __restrict__ src,
    size_t bStride, size_t hStride, size_t sStride,
    float* __restrict__ out)
{
    const int bh = blockIdx.x;
    const int b = bh >> 4, h = bh & 15;
    const float* lg = logits + (size_t)bh * SS;

    __shared__ float w[SS];
    __shared__ float redmax[8];
    __shared__ float redsum[8];
    __shared__ float red[4][DH];
    __shared__ float s_max, s_inv;

    const int tid = threadIdx.x;
    const int warp = tid >> 5, lane = tid & 31;

    // max over s
    float m = -1e30f;
    for (int s = tid; s < SS; s += 256) m = fmaxf(m, lg[s]);
#pragma unroll
    for (int o = 16; o; o >>= 1) m = fmaxf(m, __shfl_xor_sync(0xffffffffu, m, o));
    if (lane == 0) redmax[warp] = m;
    __syncthreads();
    if (tid == 0) {
        float mm = redmax[0];
#pragma unroll
        for (int i = 1; i < 8; i++) mm = fmaxf(mm, redmax[i]);
        s_max = mm;
    }
    __syncthreads();
    const float mx = s_max;

    // exp + sum
    float sum = 0.0f;
    for (int s = tid; s < SS; s += 256) {
        const float e = __expf(lg[s] - mx);
        w[s] = e;
        sum += e;
    }
#pragma unroll
    for (int o = 16; o; o >>= 1) sum += __shfl_xor_sync(0xffffffffu, sum, o);
    if (lane == 0) redsum[warp] = sum;
    __syncthreads();
    if (tid == 0) {
        float ss = 0.0f;
#pragma unroll
        for (int i = 0; i < 8; i++) ss += redsum[i];
        s_inv = 1.0f / ss;
    }
    __syncthreads();
    const float inv = s_inv;

    // weighted pooling: 64 threads along d, 4 groups along s
    const int d = tid & 63, sg = tid >> 6;
    const float* sp = src + (size_t)b * bStride + (size_t)h * hStride + d;
    float acc = 0.0f;
    for (int s = sg; s < SS; s += 4)
        acc = fmaf(w[s], sp[(size_t)s * sStride], acc);
    red[sg][d] = acc;
    __syncthreads();
    if (sg == 0)
        out[(size_t)bh * DH + d] = (red[0][d] + red[1][d] + red[2][d] + red[3][d]) * inv;
}

// ---------------------------------------------------------------------------
// QAK[b,h,s,dh] = Kp[b,s,h*64+dh] * qglob[b,h,dh]   (float4 over dh)
// ---------------------------------------------------------------------------
__global__ __launch_bounds__(256) void qak_kernel(
    const float* __restrict__ Kp, const float* __restrict__ qg,
    float* __restrict__ QAK)
{
    const size_t n4 = ELEMS / 4;
    size_t i4 = (size_t)blockIdx.x * 256 + threadIdx.x;
    if (i4 >= n4) return;
    const int d4 = (int)(i4 & 15);          // dh/4
    const int s  = (int)((i4 >> 4) & (SS - 1));
    const int bh = (int)(i4 >> 15);         // b*16+h
    const int b = bh >> 4, h = bh & 15;

    const float4 kv = *(const float4*)(Kp + ((size_t)(b * SS + s)) * DM + h * DH + d4 * 4);
    const float4 gv = *(const float4*)(qg + (size_t)bh * DH + d4 * 4);
    float4 o;
    o.x = kv.x * gv.x; o.y = kv.y * gv.y; o.z = kv.z * gv.z; o.w = kv.w * gv.w;
    *(float4*)(QAK + i4 * 4) = o;
}

// ---------------------------------------------------------------------------
extern "C" void kernel_launch(void* const* d_in, const int* in_sizes, int n_in,
                              void* d_out, int out_size)
{
    const float* Q_seq = (const float*)d_in[0];
    const float* K_seq = (const float*)d_in[1];
    // d_in[2] = V_seq (unused by the reference)
    const float* WQ = (const float*)d_in[3];
    const float* WK = (const float*)d_in[4];
    const float* Wa = (const float*)d_in[5];
    const float* Wb = (const float*)d_in[6];
    const float* WP = (const float*)d_in[7];
    float* out = (float*)d_out;

    float *pQ, *pKp, *pQAK, *pLg, *pQg, *pKg, *pWaT, *pWbT;
    cudaGetSymbolAddress((void**)&pQ,   g_Q);
    cudaGetSymbolAddress((void**)&pKp,  g_Kp);
    cudaGetSymbolAddress((void**)&pQAK, g_QAK);
    cudaGetSymbolAddress((void**)&pLg,  g_logits);
    cudaGetSymbolAddress((void**)&pQg,  g_qglob);
    cudaGetSymbolAddress((void**)&pKg,  g_kglob);
    cudaGetSymbolAddress((void**)&pWaT, g_WaT);
    cudaGetSymbolAddress((void**)&pWbT, g_WbT);

    const float scaleF = 0.125f; // 1/sqrt(64)

    // 0. transpose small weights
    transpose_w<<<(DM * NH + 255) / 256, 256>>>(Wa, pWaT);
    transpose_w<<<(DM * NH + 255) / 256, 256>>>(Wb, pWbT);

    const dim3 ggrid(DM / 128, MROWS / 128);

    // 1. Q = Q_seq @ WQ
    sgemm128<false><<<ggrid, 256>>>(Q_seq, WQ, pQ, nullptr, nullptr, MROWS, DM, DM);
    // 2. Kp = K_seq @ WK
    sgemm128<false><<<ggrid, 256>>>(K_seq, WK, pKp, nullptr, nullptr, MROWS, DM, DM);

    // 3. alpha logits = (Q @ Wa) * scale   -> [b,e,s]
    row_logits<<<MROWS, 256>>>(pQ, pWaT, pLg, scaleF);
    // 4. alpha softmax + pool over Qh -> q_glob[b,h,dh]
    softmax_pool<<<NB * NH, 256>>>(pLg, pQ,
                                   (size_t)SS * DM, (size_t)DH, (size_t)DM, pQg);

    // 5. QAK[b,h,s,dh] = Kp_heads * q_glob
    qak_kernel<<<(unsigned)((ELEMS / 4 + 255) / 256), 256>>>(pKp, pQg, pQAK);

    // 6. beta logits = (QAK_D @ Wb) * scale  (QAK flat is exactly QAK_D)
    row_logits<<<MROWS, 256>>>(pQAK, pWbT, pLg, scaleF);
    // 7. beta softmax + pool over QAK -> k_glob[b,h,dh] == [b,1024]
    softmax_pool<<<NB * NH, 256>>>(pLg, pQAK,
                                   (size_t)NH * SS * DH, (size_t)SS * DH, (size_t)DH, pKg);

    // 8. out = (Q * kglob_bcast) @ WP + Q
    sgemm128<true><<<ggrid, 256>>>(pQ, WP, out, pKg, pQ, MROWS, DM, DM);
}

// round 4
// speedup vs baseline: 2.9372x; 2.9372x over previous
#include <cuda_runtime.h>
#include <cstdint>
#include <math.h>

#define NB 8
#define SS 2048
#define DM 1024
#define NH 16
#define DH 64
#define MROWS (NB * SS)
#define ELEMS ((size_t)MROWS * DM)

__device__ float g_At[ELEMS];            // tf32-rounded A operand (reused 3x)
__device__ float g_Q[ELEMS];             // Q = Q_seq @ WQ (fp32)
__device__ float g_QAK[ELEMS];           // QAK [b,h,s,dh]
__device__ float g_WT[DM * DM];          // transposed tf32 weight (reused 3x)
__device__ float g_logits[NB * NH * SS];
__device__ float g_qglob[NB * DM];
__device__ float g_kglob[NB * DM];
__device__ float g_WaT[NH * DM];
__device__ float g_WbT[NH * DM];

// ---------------- helpers ----------------
__device__ __forceinline__ uint32_t smem_u32(const void* p) {
    uint32_t a;
    asm("{ .reg .u64 t; cvta.to.shared.u64 t, %1; cvt.u32.u64 %0, t; }" : "=r"(a) : "l"(p));
    return a;
}
__device__ __forceinline__ void cp_async16(uint32_t s, const void* g) {
    asm volatile("cp.async.cg.shared.global [%0], [%1], 16;" :: "r"(s), "l"(g));
}
__device__ __forceinline__ void cp_commit() { asm volatile("cp.async.commit_group;" ::: "memory"); }
template <int N> __device__ __forceinline__ void cp_wait() {
    asm volatile("cp.async.wait_group %0;" :: "n"(N) : "memory");
}
__device__ __forceinline__ float rna_tf32(float x) {
    float r;
    asm("cvt.rna.tf32.f32 %0, %1;" : "=f"(r) : "f"(x));
    return r;
}
__device__ __forceinline__ void mma_tf32(float* c, const uint32_t* a, const uint32_t* b) {
    asm volatile(
        "mma.sync.aligned.m16n8k8.row.col.f32.tf32.tf32.f32 "
        "{%0,%1,%2,%3}, {%4,%5,%6,%7}, {%8,%9}, {%0,%1,%2,%3};"
        : "+f"(c[0]), "+f"(c[1]), "+f"(c[2]), "+f"(c[3])
        : "r"(a[0]), "r"(a[1]), "r"(a[2]), "r"(a[3]), "r"(b[0]), "r"(b[1]));
}

// ---------------- mma.sync tf32 GEMM ----------------
// C[M,N] = A[M,K] @ Bt[N,K]^T ; M=16384, N=1024, K=1024.
// BM=BN=128, BK=32, 256 threads, warp tile 32x64, 3-stage cp.async ring.
#define BKF 32
#define ASTR 36                          // 32 + 4 pad floats
#define TILE_F (128 * ASTR)              // floats per A (or B) tile
#define STAGE_F (2 * TILE_F)
#define NST 3
#define KITERS (DM / BKF)                // 32
#define DYN_SMEM (NST * STAGE_F * 4)     // 110592 B

// MODE 0: plain store. MODE 1: scale by aux[b,n], scatter to [b,h,s,dh]. MODE 2: + aux residual.
template <int MODE>
__global__ __launch_bounds__(256, 2) void gemm_mma(
    const float* __restrict__ A, const float* __restrict__ Bt,
    float* __restrict__ C, const float* __restrict__ aux)
{
    extern __shared__ float sm[];
    const uint32_t sbase = smem_u32(sm);
    const int tid = threadIdx.x;
    const int wid = tid >> 5, lane = tid & 31;
    const int warpM = wid & 3, warpN = wid >> 2;      // 4 x 2 warp grid
    const int grp = lane >> 2, qid = lane & 3;
    const int rowM = blockIdx.y * 128, rowN = blockIdx.x * 128;

    float acc[2][8][4];
#pragma unroll
    for (int i = 0; i < 2; i++)
#pragma unroll
        for (int j = 0; j < 8; j++)
#pragma unroll
            for (int l = 0; l < 4; l++) acc[i][j][l] = 0.0f;

    // prefetch one stage (A tile + B tile), 4 granules each per thread
    auto prefetch = [&](int kt, int slot) {
        const uint32_t sA = sbase + (uint32_t)slot * STAGE_F * 4;
        const uint32_t sB = sA + TILE_F * 4;
        const int kbase = kt * BKF;
#pragma unroll
        for (int j = 0; j < 4; j++) {
            const int t = tid + j * 256;
            const int row = t >> 3, g = t & 7;
            cp_async16(sA + (uint32_t)(row * ASTR + g * 4) * 4,
                       A + (size_t)(rowM + row) * DM + kbase + g * 4);
        }
#pragma unroll
        for (int j = 0; j < 4; j++) {
            const int t = tid + j * 256;
            const int row = t >> 3, g = t & 7;
            cp_async16(sB + (uint32_t)(row * ASTR + g * 4) * 4,
                       Bt + (size_t)(rowN + row) * DM + kbase + g * 4);
        }
        cp_commit();
    };

    prefetch(0, 0);
    prefetch(1, 1);

    for (int kt = 0; kt < KITERS; kt++) {
        if (kt < KITERS - 1) cp_wait<1>(); else cp_wait<0>();
        __syncthreads();
        if (kt + 2 < KITERS) prefetch(kt + 2, (kt + 2) % NST);

        const float* As = sm + (kt % NST) * STAGE_F;
        const float* Bs = As + TILE_F;
#pragma unroll
        for (int ks = 0; ks < 4; ks++) {
            const int c = ks * 8 + qid;
            uint32_t afr[2][4], bfr[8][2];
#pragma unroll
            for (int mt = 0; mt < 2; mt++) {
                const int r = warpM * 32 + mt * 16 + grp;
                afr[mt][0] = __float_as_uint(As[r * ASTR + c]);
                afr[mt][1] = __float_as_uint(As[(r + 8) * ASTR + c]);
                afr[mt][2] = __float_as_uint(As[r * ASTR + c + 4]);
                afr[mt][3] = __float_as_uint(As[(r + 8) * ASTR + c + 4]);
            }
#pragma unroll
            for (int nt = 0; nt < 8; nt++) {
                const int n = warpN * 64 + nt * 8 + grp;
                bfr[nt][0] = __float_as_uint(Bs[n * ASTR + c]);
                bfr[nt][1] = __float_as_uint(Bs[n * ASTR + c + 4]);
            }
#pragma unroll
            for (int mt = 0; mt < 2; mt++)
#pragma unroll
                for (int nt = 0; nt < 8; nt++)
                    mma_tf32(acc[mt][nt], afr[mt], bfr[nt]);
        }
    }

    // Epilogue
    const int bB = rowM >> 11;                         // batch constant per block
#pragma unroll
    for (int mt = 0; mt < 2; mt++) {
        const int r0 = rowM + warpM * 32 + mt * 16 + grp;
        const int r1 = r0 + 8;
        const int s0 = r0 & (SS - 1), s1 = r1 & (SS - 1);
#pragma unroll
        for (int nt = 0; nt < 8; nt++) {
            const int n = rowN + warpN * 64 + nt * 8 + qid * 2;
            const float* a4 = acc[mt][nt];
            if (MODE == 0) {
                *(float2*)(C + (size_t)r0 * DM + n) = make_float2(a4[0], a4[1]);
                *(float2*)(C + (size_t)r1 * DM + n) = make_float2(a4[2], a4[3]);
            } else if (MODE == 1) {
                const int h = n >> 6, d = n & 63;
                const float2 g = *(const float2*)(aux + (size_t)bB * DM + n);
                float* base = C + (((size_t)(bB * NH + h)) << 17) + d;  // *2048*64
                *(float2*)(base + (size_t)s0 * DH) = make_float2(a4[0] * g.x, a4[1] * g.y);
                *(float2*)(base + (size_t)s1 * DH) = make_float2(a4[2] * g.x, a4[3] * g.y);
            } else {
                const float2 q0 = *(const float2*)(aux + (size_t)r0 * DM + n);
                const float2 q1 = *(const float2*)(aux + (size_t)r1 * DM + n);
                *(float2*)(C + (size_t)r0 * DM + n) = make_float2(a4[0] + q0.x, a4[1] + q0.y);
                *(float2*)(C + (size_t)r1 * DM + n) = make_float2(a4[2] + q1.x, a4[3] + q1.y);
            }
        }
    }
}

// ---------------- conversion / small kernels ----------------
__global__ __launch_bounds__(256) void conv_rna(
    const float4* __restrict__ in, float4* __restrict__ out)
{
    const size_t i = (size_t)blockIdx.x * 256 + threadIdx.x;
    float4 v = in[i];
    v.x = rna_tf32(v.x); v.y = rna_tf32(v.y);
    v.z = rna_tf32(v.z); v.w = rna_tf32(v.w);
    out[i] = v;
}

__global__ __launch_bounds__(256) void conv_scale_rna(
    const float4* __restrict__ Q, const float* __restrict__ kg,
    float4* __restrict__ out)
{
    const size_t i = (size_t)blockIdx.x * 256 + threadIdx.x;
    const int c4 = (int)(i & 255);
    const int b  = (int)(i >> 19);
    const float4 g = *(const float4*)(kg + (size_t)b * DM + c4 * 4);
    float4 v = Q[i];
    v.x = rna_tf32(v.x * g.x); v.y = rna_tf32(v.y * g.y);
    v.z = rna_tf32(v.z * g.z); v.w = rna_tf32(v.w * g.w);
    out[i] = v;
}

__global__ void transpose_rna(const float* __restrict__ W, float* __restrict__ WT)
{
    __shared__ float t[32][33];
    const int x0 = blockIdx.x * 32, y0 = blockIdx.y * 32;
    const int tx = threadIdx.x, ty = threadIdx.y;  // 32 x 8
#pragma unroll
    for (int j = 0; j < 32; j += 8)
        t[ty + j][tx] = W[(size_t)(y0 + ty + j) * DM + x0 + tx];
    __syncthreads();
#pragma unroll
    for (int j = 0; j < 32; j += 8)
        WT[(size_t)(x0 + ty + j) * DM + y0 + tx] = rna_tf32(t[tx][ty + j]);
}

__global__ void transpose_w(const float* __restrict__ W, float* __restrict__ WT)
{
    int i = blockIdx.x * 256 + threadIdx.x;
    if (i < DM * NH) {
        int j = i >> 4, e = i & 15;
        WT[e * DM + j] = W[i];
    }
}

__global__ __launch_bounds__(256) void row_logits(
    const float* __restrict__ rows, const float* __restrict__ WT,
    float* __restrict__ logits, float scaleF)
{
    const int r = blockIdx.x;
    __shared__ float4 srow[DM / 4];
    const int tid = threadIdx.x;
    srow[tid] = ((const float4*)(rows + (size_t)r * DM))[tid];
    __syncthreads();

    const int warp = tid >> 5, lane = tid & 31;
#pragma unroll
    for (int e = warp; e < NH; e += 8) {
        const float4* w4 = (const float4*)(WT + (size_t)e * DM);
        float4 a = make_float4(0.f, 0.f, 0.f, 0.f);
        for (int j = lane; j < DM / 4; j += 32) {
            const float4 sv = srow[j], wv = w4[j];
            a.x = fmaf(sv.x, wv.x, a.x); a.y = fmaf(sv.y, wv.y, a.y);
            a.z = fmaf(sv.z, wv.z, a.z); a.w = fmaf(sv.w, wv.w, a.w);
        }
        float p = (a.x + a.y) + (a.z + a.w);
#pragma unroll
        for (int o = 16; o; o >>= 1) p += __shfl_xor_sync(0xffffffffu, p, o);
        if (lane == 0) {
            const int b = r >> 11, s = r & (SS - 1);
            logits[((size_t)(b * NH + e)) * SS + s] = p * scaleF;
        }
    }
}

__global__ __launch_bounds__(256) void softmax_pool(
    const float* __restrict__ logits, const float* __restrict__ src,
    size_t bStride, size_t hStride, size_t sStride,
    float* __restrict__ out)
{
    const int bh = blockIdx.x;
    const int b = bh >> 4, h = bh & 15;
    const float* lg = logits + (size_t)bh * SS;

    __shared__ float w[SS];
    __shared__ float redm[8], reds[8];
    __shared__ float4 red4[16][16];
    __shared__ float s_max, s_inv;

    const int tid = threadIdx.x;
    const int warp = tid >> 5, lane = tid & 31;

    float m = -1e30f;
    for (int s = tid; s < SS; s += 256) m = fmaxf(m, lg[s]);
#pragma unroll
    for (int o = 16; o; o >>= 1) m = fmaxf(m, __shfl_xor_sync(0xffffffffu, m, o));
    if (lane == 0) redm[warp] = m;
    __syncthreads();
    if (tid == 0) {
        float mm = redm[0];
#pragma unroll
        for (int i = 1; i < 8; i++) mm = fmaxf(mm, redm[i]);
        s_max = mm;
    }
    __syncthreads();
    const float mx = s_max;

    float sum = 0.0f;
    for (int s = tid; s < SS; s += 256) {
        const float e = __expf(lg[s] - mx);
        w[s] = e;
        sum += e;
    }
#pragma unroll
    for (int o = 16; o; o >>= 1) sum += __shfl_xor_sync(0xffffffffu, sum, o);
    if (lane == 0) reds[warp] = sum;
    __syncthreads();
    if (tid == 0) {
        float ss = 0.0f;
#pragma unroll
        for (int i = 0; i < 8; i++) ss += reds[i];
        s_inv = 1.0f / ss;
    }
    __syncthreads();
    const float inv = s_inv;

    const int d4 = tid & 15, sg = tid >> 4;
    const float* sp = src + (size_t)b * bStride + (size_t)h * hStride + d4 * 4;
    float4 acc = make_float4(0.f, 0.f, 0.f, 0.f);
    for (int s = sg; s < SS; s += 16) {
        const float4 v = *(const float4*)(sp + (size_t)s * sStride);
        const float ws = w[s];
        acc.x = fmaf(ws, v.x, acc.x); acc.y = fmaf(ws, v.y, acc.y);
        acc.z = fmaf(ws, v.z, acc.z); acc.w = fmaf(ws, v.w, acc.w);
    }
    red4[sg][d4] = acc;
    __syncthreads();
    if (sg == 0) {
        float4 t = red4[0][d4];
#pragma unroll
        for (int g = 1; g < 16; g++) {
            const float4 u = red4[g][d4];
            t.x += u.x; t.y += u.y; t.z += u.z; t.w += u.w;
        }
        *(float4*)(out + (size_t)bh * DH + d4 * 4) =
            make_float4(t.x * inv, t.y * inv, t.z * inv, t.w * inv);
    }
}

// ---------------------------------------------------------------------------
extern "C" void kernel_launch(void* const* d_in, const int* in_sizes, int n_in,
                              void* d_out, int out_size)
{
    const float* Q_seq = (const float*)d_in[0];
    const float* K_seq = (const float*)d_in[1];
    const float* WQ = (const float*)d_in[3];
    const float* WK = (const float*)d_in[4];
    const float* Wa = (const float*)d_in[5];
    const float* Wb = (const float*)d_in[6];
    const float* WP = (const float*)d_in[7];
    float* out = (float*)d_out;

    float *pAt, *pQ, *pQAK, *pWT, *pLg, *pQg, *pKg, *pWaT, *pWbT;
    cudaGetSymbolAddress((void**)&pAt,  g_At);
    cudaGetSymbolAddress((void**)&pQ,   g_Q);
    cudaGetSymbolAddress((void**)&pQAK, g_QAK);
    cudaGetSymbolAddress((void**)&pWT,  g_WT);
    cudaGetSymbolAddress((void**)&pLg,  g_logits);
    cudaGetSymbolAddress((void**)&pQg,  g_qglob);
    cudaGetSymbolAddress((void**)&pKg,  g_kglob);
    cudaGetSymbolAddress((void**)&pWaT, g_WaT);
    cudaGetSymbolAddress((void**)&pWbT, g_WbT);

    cudaFuncSetAttribute(gemm_mma<0>, cudaFuncAttributeMaxDynamicSharedMemorySize, DYN_SMEM);
    cudaFuncSetAttribute(gemm_mma<1>, cudaFuncAttributeMaxDynamicSharedMemorySize, DYN_SMEM);
    cudaFuncSetAttribute(gemm_mma<2>, cudaFuncAttributeMaxDynamicSharedMemorySize, DYN_SMEM);

    const float scaleF = 0.125f;
    const dim3 ggrid(DM / 128, MROWS / 128);     // (8, 128)
    const dim3 tgrid(32, 32), tblk(32, 8);
    const unsigned cgrid = (unsigned)(ELEMS / 4 / 256);

    transpose_w<<<(DM * NH + 255) / 256, 256>>>(Wa, pWaT);
    transpose_w<<<(DM * NH + 255) / 256, 256>>>(Wb, pWbT);

    // 1. Q = Q_seq @ WQ (tf32 tensor)
    conv_rna<<<cgrid, 256>>>((const float4*)Q_seq, (float4*)pAt);
    transpose_rna<<<tgrid, tblk>>>(WQ, pWT);
    gemm_mma<0><<<ggrid, 256, DYN_SMEM>>>(pAt, pWT, pQ, nullptr);

    // 2. alpha = softmax(Q @ Wa * scale); q_glob = pool(alpha, Qh)
    row_logits<<<MROWS, 256>>>(pQ, pWaT, pLg, scaleF);
    softmax_pool<<<NB * NH, 256>>>(pLg, pQ,
                                   (size_t)SS * DM, (size_t)DH, (size_t)DM, pQg);

    // 3. QAK = (K_seq @ WK) * q_glob, scattered to [b,h,s,dh]
    conv_rna<<<cgrid, 256>>>((const float4*)K_seq, (float4*)pAt);
    transpose_rna<<<tgrid, tblk>>>(WK, pWT);
    gemm_mma<1><<<ggrid, 256, DYN_SMEM>>>(pAt, pWT, pQAK, pQg);

    // 4. beta = softmax(QAK_D @ Wb * scale); k_glob = pool(beta, QAK)
    row_logits<<<MROWS, 256>>>(pQAK, pWbT, pLg, scaleF);
    softmax_pool<<<NB * NH, 256>>>(pLg, pQAK,
                                   (size_t)NH * SS * DH, (size_t)SS * DH, (size_t)DH, pKg);

    // 5. out = (Q * k_glob) @ WP + Q
    conv_scale_rna<<<cgrid, 256>>>((const float4*)pQ, pKg, (float4*)pAt);
    transpose_rna<<<tgrid, tblk>>>(WP, pWT);
    gemm_mma<2><<<ggrid, 256, DYN_SMEM>>>(pAt, pWT, out, pQ);
}